// round 9
// baseline (speedup 1.0000x reference)
#include <cuda_runtime.h>
#include <math.h>

#define H 4096
#define HS 64
#define NH 64
#define TM 64
#define TD 128
#define GRID 296
#define NT 512

// ---------------- scratch (device globals) ----------------
__device__ float g_xn[H];
__device__ float g_sx[H];
__device__ float g_maa_part[128][5 * TM];
__device__ float g_m[5][H];
__device__ float g_partC[4 * 64 * H];      // 4 mats x 64 splits x 4096 (4 MB)
__device__ float g_wd1_part[64][TD];
__device__ float g_wo_part[128 * H];       // 128 splits x 4096 (2 MB)
__device__ float g_gx[H];

__device__ unsigned long long g_bar = 0ULL;
__device__ unsigned int g_tickC;
__device__ unsigned int g_tickE;
__device__ unsigned int g_headflag[NH];

__global__ void k_reset(void) {
    int t = threadIdx.x;
    if (t == 0) { g_tickC = 0u; g_tickE = 0u; }
    if (t < NH) g_headflag[t] = 0u;
}

__device__ __forceinline__ void grid_barrier() {
    __syncthreads();
    if (threadIdx.x == 0) {
        __threadfence();
        unsigned long long ticket = atomicAdd(&g_bar, 1ULL);
        unsigned long long goal = (ticket / GRID + 1ULL) * GRID;
        while (*((volatile unsigned long long*)&g_bar) < goal) { }
        __threadfence();
    }
    __syncthreads();
}

__device__ __forceinline__ void f4_fma(float4& a, float m, const float4& w) {
    a.x += m * w.x; a.y += m * w.y; a.z += m * w.z; a.w += m * w.w;
}

__global__ __launch_bounds__(NT, 2)
void k_mega(const float* __restrict__ x,
            const float* __restrict__ s1,
            const float* __restrict__ state2,
            const float* __restrict__ ln1_w,
            const float* __restrict__ ln1_b,
            const float* __restrict__ tmx,
            const float* __restrict__ tmw,
            const float* __restrict__ tmk,
            const float* __restrict__ tmv,
            const float* __restrict__ tmr,
            const float* __restrict__ tmg,
            const float* __restrict__ Wmaa1,
            const float* __restrict__ Wmaa2,
            const float* __restrict__ tdec,
            const float* __restrict__ Wd1,
            const float* __restrict__ Wd2,
            const float* __restrict__ faaaa,
            const float* __restrict__ Wr,
            const float* __restrict__ Wk,
            const float* __restrict__ Wv,
            const float* __restrict__ Wg,
            const float* __restrict__ Wo,
            const float* __restrict__ lnxw,
            const float* __restrict__ lnxb,
            float* __restrict__ d_out) {
    __shared__ __align__(16) float sm[5120];   // 20 KB scratch
    __shared__ unsigned s_u;
    int t = threadIdx.x;
    int b = blockIdx.x;

    // ================= Phase A: LN stats (redundant) + token shift + maa1 partials ====
    {
        float lsum = 0.f, lsq = 0.f;
        const float4* x4 = reinterpret_cast<const float4*>(x);
#pragma unroll
        for (int i = t; i < 1024; i += NT) {
            float4 v = x4[i];
            lsum += v.x + v.y + v.z + v.w;
            lsq += v.x * v.x + v.y * v.y + v.z * v.z + v.w * v.w;
        }
        sm[t] = lsum; sm[512 + t] = lsq;
        __syncthreads();
        for (int s = 256; s > 0; s >>= 1) {
            if (t < s) { sm[t] += sm[t + s]; sm[512 + t] += sm[512 + t + s]; }
            __syncthreads();
        }
        float mean = sm[0] * (1.0f / H);
        float var = sm[512] * (1.0f / H) - mean * mean;
        float rs = rsqrtf(var + 1e-5f);
        __syncthreads();

        int c = b;                       // 128 chunks of 32 rows; blocks 128+ idle
        if (c < 128) {
            if (t < 32) {
                int i = c * 32 + t;
                float xn = (x[i] - mean) * rs * ln1_w[i] + ln1_b[i];
                float sx = s1[i] - xn;
                g_xn[i] = xn;
                g_sx[i] = sx;
                d_out[H + i] = xn;       // state1_out
                sm[1024 + t] = xn + sx * tmx[i];
            }
            __syncthreads();
            if (t < 320) {
                float acc = 0.f;
#pragma unroll 8
                for (int i = 0; i < 32; i++)
                    acc += sm[1024 + i] * Wmaa1[(size_t)(c * 32 + i) * 320 + t];
                g_maa_part[c][t] = acc;
            }
        }
    }
    grid_barrier();

    // ================= Phase B: mix = tanh(reduce), m = xn + sx*(mix@Wmaa2 + maa) =====
    {
        int u = b;                       // 80 units: 5 s-heads x 16 col-chunks
        if (u < 80) {
            int s5 = u >> 4, chunk = u & 15;
            int tt = t & 63, seg = t >> 6;
            float a = 0.f;
#pragma unroll
            for (int cc = seg * 16; cc < seg * 16 + 16; cc++)
                a += g_maa_part[cc][s5 * 64 + tt];
            sm[t] = a;
            __syncthreads();
            if (t < 64) {
                float m = sm[t];
#pragma unroll
                for (int g2 = 1; g2 < 8; g2++) m += sm[g2 * 64 + t];
                sm[512 + t] = tanhf(m);
            }
            __syncthreads();
            if (t < 256) {
                int hh = chunk * 256 + t;
                float acc = 0.f;
#pragma unroll 8
                for (int e = 0; e < 64; e++)
                    acc += sm[512 + e] * Wmaa2[(size_t)(s5 * 64 + e) * H + hh];
                const float* maa = (s5 == 0) ? tmw : (s5 == 1) ? tmk : (s5 == 2) ? tmv
                                  : (s5 == 3) ? tmr : tmg;
                g_m[s5][hh] = g_xn[hh] + g_sx[hh] * (acc + maa[hh]);
            }
        }
    }
    grid_barrier();

    // ================= Phase C: row-contiguous split-K streaming (ticket) =============
    // units 0..255: (mat = u&3, split = u>>2); 64 rows x full 16KB row -> partials.
    // units 256..319: Wd1 splits.
    for (;;) {
        __syncthreads();
        if (t == 0) s_u = atomicAdd(&g_tickC, 1u);
        __syncthreads();
        unsigned u = s_u;
        if (u >= 320u) break;
        if (u < 256u) {
            int mat = u & 3;
            int split = u >> 2;          // 0..63, rows [split*64, +64)
            const float* vec = (mat == 0) ? g_m[3] : (mat == 1) ? g_m[1]
                              : (mat == 2) ? g_m[2] : g_m[4];
            const float* W = (mat == 0) ? Wr : (mat == 1) ? Wk : (mat == 2) ? Wv : Wg;
            if (t < 64) sm[t] = vec[split * 64 + t];
            __syncthreads();
            const float4* W4 = reinterpret_cast<const float4*>(W);
            int c0 = t, c1 = t + 512;    // two contiguous 8KB halves of each row
            float4 a0 = make_float4(0.f, 0.f, 0.f, 0.f);
            float4 a1 = make_float4(0.f, 0.f, 0.f, 0.f);
#pragma unroll 8
            for (int i = 0; i < 64; i++) {
                size_t rb = (size_t)(split * 64 + i) * 1024;
                float m = sm[i];
                f4_fma(a0, m, W4[rb + c0]);
                f4_fma(a1, m, W4[rb + c1]);
            }
            float4* P = reinterpret_cast<float4*>(&g_partC[(size_t)(mat * 64 + split) * H]);
            P[c0] = a0;
            P[c1] = a1;
        } else {
            int split = (int)u - 256;    // 64 rows
            int col = t & 127, seg = t >> 7;   // 4 segs x 16 rows
            const float* vrow = g_m[0] + split * 64 + seg * 16;
            float acc = 0.f;
#pragma unroll
            for (int i = 0; i < 16; i++)
                acc += vrow[i] * Wd1[(size_t)(split * 64 + seg * 16 + i) * TD + col];
            sm[1024 + t] = acc;
            __syncthreads();
            if (t < TD)
                g_wd1_part[split][t] = sm[1024 + t] + sm[1024 + t + 128]
                                     + sm[1024 + t + 256] + sm[1024 + t + 384];
        }
    }
    grid_barrier();

    // ================= Phase D: blocks 0..63 — inline reduce + decay + heads ==========
    // Other blocks fall through to Phase E and spin on per-head flags.
    {
        int h = b;
        if (h < 64) {
            int base = h * HS;
            float* r_s = sm + 1152;
            float* k_s = sm + 1216;
            float* v_s = sm + 1280;
            float* td_s = sm + 1344;
            float* prod = sm + 1408;
            float* part = sm + 1472;   // 512
            float* red = sm + 1984;
            float* red2 = sm + 2048;
            float* g_s = sm + 2112;

            // inline rkvg reduce for this head's 256 (mat,col) pairs
            {
                int pair = t >> 1;           // 0..255
                int hseg = t & 1;            // 2 segs of 32 splits
                int mat = pair >> 6;
                int col = pair & 63;
                float a = 0.f;
#pragma unroll 8
                for (int s = hseg * 32; s < hseg * 32 + 32; s++)
                    a += g_partC[(size_t)(mat * 64 + s) * H + base + col];
                sm[t] = a;
            }
            __syncthreads();
            if (t < 256) {
                int mat = t >> 6, col = t & 63;
                float v = sm[2 * t] + sm[2 * t + 1];
                if (mat == 0) r_s[col] = v;
                else if (mat == 1) k_s[col] = v;
                else if (mat == 2) v_s[col] = v;
                else g_s[col] = v / (1.0f + expf(-v));    // silu gate
            }
            __syncthreads();

            // wd1 reduce -> tanh
            {
                int col = t & 127, sg = t >> 7;    // 4 segs x 16 splits
                float a = 0.f;
#pragma unroll
                for (int s = sg * 16; s < sg * 16 + 16; s++)
                    a += g_wd1_part[s][col];
                sm[t] = a;
            }
            __syncthreads();
            if (t < TD)
                sm[512 + t] = tanhf(sm[t] + sm[t + 128] + sm[t + 256] + sm[t + 384]);
            __syncthreads();
            // Wd2 stripe for this head's 64 cols
            {
                int d = t & 63, sg = t >> 6;       // 8 segs x 16 e
                float a = 0.f;
#pragma unroll
                for (int e = sg * 16; e < sg * 16 + 16; e++)
                    a += sm[512 + e] * Wd2[(size_t)e * H + base + d];
                sm[640 + t] = a;
            }
            __syncthreads();
            if (t < 64) {
                float s = sm[640 + t] + sm[640 + 64 + t] + sm[640 + 128 + t] + sm[640 + 192 + t]
                        + sm[640 + 256 + t] + sm[640 + 320 + t] + sm[640 + 384 + t] + sm[640 + 448 + t];
                td_s[t] = expf(-expf(tdec[base + t] + s));
                prod[t] = r_s[t] * k_s[t] * faaaa[base + t];
            }
            __syncthreads();
            if (t < 32) prod[t] += prod[t + 32];
            __syncthreads();
            if (t < 16) prod[t] += prod[t + 16];
            __syncthreads();
            if (t < 8) prod[t] += prod[t + 8];
            __syncthreads();
            if (t < 4) prod[t] += prod[t + 4];
            __syncthreads();
            if (t < 2) prod[t] += prod[t + 2];
            __syncthreads();
            if (t == 0) prod[0] += prod[1];
            __syncthreads();
            float dot1 = prod[0];

            int d = t & 63, q = t >> 6;            // 8 groups x 8 kk
            const float* s2 = state2 + (size_t)h * HS * HS;
            float* s2o = d_out + 2 * H + (size_t)h * HS * HS;
            float vv = v_s[d];
            float acc = 0.f;
#pragma unroll
            for (int kk = q * 8; kk < q * 8 + 8; kk++) {
                float s2v = s2[kk * HS + d];
                acc += r_s[kk] * s2v;
                s2o[kk * HS + d] = k_s[kk] * vv + s2v * td_s[kk];
            }
            part[q * 64 + d] = acc;
            __syncthreads();

            if (t < 64) {
                float out_d = v_s[t] * dot1;
#pragma unroll
                for (int q2 = 0; q2 < 8; q2++) out_d += part[q2 * 64 + t];
                red[t] = out_d;
                red2[t] = out_d * out_d;
                part[t] = out_d;   // stash
            }
            __syncthreads();
            if (t < 32) { red[t] += red[t + 32]; red2[t] += red2[t + 32]; }
            __syncthreads();
            if (t < 16) { red[t] += red[t + 16]; red2[t] += red2[t + 16]; }
            __syncthreads();
            if (t < 8) { red[t] += red[t + 8]; red2[t] += red2[t + 8]; }
            __syncthreads();
            if (t < 4) { red[t] += red[t + 4]; red2[t] += red2[t + 4]; }
            __syncthreads();
            if (t < 2) { red[t] += red[t + 2]; red2[t] += red2[t + 2]; }
            __syncthreads();
            if (t == 0) { red[0] += red[1]; red2[0] += red2[1]; }
            __syncthreads();
            if (t < 64) {
                float mean = red[0] * (1.0f / HS);
                float var = red2[0] * (1.0f / HS) - mean * mean;
                float o = (part[t] - mean) * rsqrtf(var + 1e-5f) * lnxw[base + t] + lnxb[base + t];
                g_gx[base + t] = o * g_s[t];
            }
            __syncthreads();
            if (t == 0) {
                __threadfence();
                *((volatile unsigned*)&g_headflag[h]) = 1u;
            }
        }
    }
    // NO barrier: non-D blocks proceed to E and spin on flags (D blocks join after).

    // ================= Phase E: Wo split-K streaming (ticket, flag-gated) =============
    // 256 units: split = u>>1 (0..127, 32 rows each), half = u&1 (8KB of the row).
    for (;;) {
        __syncthreads();
        if (t == 0) s_u = atomicAdd(&g_tickE, 1u);
        __syncthreads();
        unsigned u = s_u;
        if (u >= 256u) break;
        int split = (int)(u >> 1);
        int halfc = (int)(u & 1);
        int head = split >> 1;
        if (t == 0) {
            while (*((volatile unsigned*)&g_headflag[head]) == 0u) { }
        }
        __syncthreads();
        if (t < 32) sm[t] = __ldcg(&g_gx[split * 32 + t]);
        __syncthreads();
        const float4* W4 = reinterpret_cast<const float4*>(Wo);
        int col = halfc * 512 + t;        // f4 col; block covers contiguous 8KB per row
        float4 a = make_float4(0.f, 0.f, 0.f, 0.f);
#pragma unroll 8
        for (int i = 0; i < 32; i++) {
            size_t rb = (size_t)(split * 32 + i) * 1024;
            f4_fma(a, sm[i], W4[rb + col]);
        }
        reinterpret_cast<float4*>(&g_wo_part[(size_t)split * H])[col] = a;
    }
    grid_barrier();

    // ================= Phase F: Wo reduce + residual (blocks 0..63) ===================
    {
        if (b < 64) {
            int col = t & 63, q = t >> 6;      // 8 groups x 16 splits
            int j = b * 64 + col;
            float a = 0.f;
#pragma unroll
            for (int s = q * 16; s < q * 16 + 16; s++)
                a += g_wo_part[(size_t)s * H + j];
            sm[t] = a;
            __syncthreads();
            if (t < 64) {
                float v = sm[t];
#pragma unroll
                for (int q2 = 1; q2 < 8; q2++) v += sm[q2 * 64 + t];
                d_out[j] = x[j] + v;
            }
        }
    }
}

extern "C" void kernel_launch(void* const* d_in, const int* in_sizes, int n_in,
                              void* d_out, int out_size) {
    const float* x      = (const float*)d_in[0];
    const float* state1 = (const float*)d_in[1];
    const float* state2 = (const float*)d_in[2];
    const float* ln1_w  = (const float*)d_in[3];
    const float* ln1_b  = (const float*)d_in[4];
    const float* tmx    = (const float*)d_in[5];
    const float* tmw    = (const float*)d_in[6];
    const float* tmk    = (const float*)d_in[7];
    const float* tmv    = (const float*)d_in[8];
    const float* tmr    = (const float*)d_in[9];
    const float* tmg    = (const float*)d_in[10];
    const float* Wmaa1  = (const float*)d_in[11];
    const float* Wmaa2  = (const float*)d_in[12];
    const float* tdec   = (const float*)d_in[13];
    const float* Wd1    = (const float*)d_in[14];
    const float* Wd2    = (const float*)d_in[15];
    const float* faaaa  = (const float*)d_in[16];
    const float* Wr     = (const float*)d_in[17];
    const float* Wk     = (const float*)d_in[18];
    const float* Wv     = (const float*)d_in[19];
    const float* Wg     = (const float*)d_in[20];
    const float* Wo     = (const float*)d_in[21];
    const float* lnxw   = (const float*)d_in[22];
    const float* lnxb   = (const float*)d_in[23];
    float* out = (float*)d_out;

    k_reset<<<1, 128>>>();
    k_mega<<<GRID, NT>>>(x, state1, state2, ln1_w, ln1_b, tmx, tmw, tmk, tmv, tmr, tmg,
                         Wmaa1, Wmaa2, tdec, Wd1, Wd2, faaaa, Wr, Wk, Wv, Wg, Wo,
                         lnxw, lnxb, out);
}